// round 2
// baseline (speedup 1.0000x reference)
#include <cuda_runtime.h>

#define NN 100000
#define DIM 64
#define NE 1250000

// scratch for h2 = x @ W2 (25.6 MB) — static device global, no allocation
__device__ float g_h2[NN * DIM];

// ---------------------------------------------------------------------------
// Kernel 1: dual GEMM. h1 = x@W1 -> out, h2 = x@W2 -> g_h2.
// Block: 256 threads handles 32 rows. Each thread: 1 row x 8 cols x 2 mats.
// W1/W2 staged in smem (16KB each), x rows staged in smem.
// ---------------------------------------------------------------------------
__global__ __launch_bounds__(256) void gemm_dual(
    const float* __restrict__ x,
    const float* __restrict__ W1,
    const float* __restrict__ W2,
    float* __restrict__ h1,
    float* __restrict__ h2)
{
    __shared__ float sW1[64][64];
    __shared__ float sW2[64][64];
    __shared__ float sx[32][65];   // +1 pad to kill bank conflicts on row reads

    const int tid = threadIdx.x;

    // stage weights: 4096 floats each, vectorized
    const float4* w1v = (const float4*)W1;
    const float4* w2v = (const float4*)W2;
    #pragma unroll
    for (int i = tid; i < 1024; i += 256) {
        ((float4*)&sW1[0][0])[i] = w1v[i];
        ((float4*)&sW2[0][0])[i] = w2v[i];
    }

    // stage 32 rows of x (2048 floats = 512 float4)
    const int rowBase = blockIdx.x * 32;
    const float4* x4 = (const float4*)(x + (size_t)rowBase * DIM);
    #pragma unroll
    for (int i = tid; i < 512; i += 256) {
        float4 v = x4[i];
        int r = i >> 4;
        int c = (i & 15) * 4;
        sx[r][c + 0] = v.x;
        sx[r][c + 1] = v.y;
        sx[r][c + 2] = v.z;
        sx[r][c + 3] = v.w;
    }
    __syncthreads();

    const int r  = tid >> 3;        // 0..31 local row
    const int cg = (tid & 7) * 8;   // col base 0,8,...,56

    float a1[8], a2[8];
    #pragma unroll
    for (int j = 0; j < 8; j++) { a1[j] = 0.f; a2[j] = 0.f; }

    #pragma unroll 8
    for (int k = 0; k < 64; k++) {
        float xv = sx[r][k];
        float4 wa = *(const float4*)&sW1[k][cg];
        float4 wb = *(const float4*)&sW1[k][cg + 4];
        float4 wc = *(const float4*)&sW2[k][cg];
        float4 wd = *(const float4*)&sW2[k][cg + 4];
        a1[0] = fmaf(xv, wa.x, a1[0]);
        a1[1] = fmaf(xv, wa.y, a1[1]);
        a1[2] = fmaf(xv, wa.z, a1[2]);
        a1[3] = fmaf(xv, wa.w, a1[3]);
        a1[4] = fmaf(xv, wb.x, a1[4]);
        a1[5] = fmaf(xv, wb.y, a1[5]);
        a1[6] = fmaf(xv, wb.z, a1[6]);
        a1[7] = fmaf(xv, wb.w, a1[7]);
        a2[0] = fmaf(xv, wc.x, a2[0]);
        a2[1] = fmaf(xv, wc.y, a2[1]);
        a2[2] = fmaf(xv, wc.z, a2[2]);
        a2[3] = fmaf(xv, wc.w, a2[3]);
        a2[4] = fmaf(xv, wd.x, a2[4]);
        a2[5] = fmaf(xv, wd.y, a2[5]);
        a2[6] = fmaf(xv, wd.z, a2[6]);
        a2[7] = fmaf(xv, wd.w, a2[7]);
    }

    const size_t row = (size_t)rowBase + r;   // 100000 % 32 = 0 at grid 3125? no: 3125*32=100000 exact
    float* o1 = h1 + row * DIM + cg;
    float* o2 = h2 + row * DIM + cg;
    ((float4*)o1)[0] = make_float4(a1[0], a1[1], a1[2], a1[3]);
    ((float4*)o1)[1] = make_float4(a1[4], a1[5], a1[6], a1[7]);
    ((float4*)o2)[0] = make_float4(a2[0], a2[1], a2[2], a2[3]);
    ((float4*)o2)[1] = make_float4(a2[4], a2[5], a2[6], a2[7]);
}

// ---------------------------------------------------------------------------
// Kernel 2: edge scatter. 16 threads per edge; each thread moves one float4
// via red.global.add.v4.f32 (single 128-bit L2 reduction).
// ---------------------------------------------------------------------------
__global__ __launch_bounds__(256) void scatter_edges(
    const int* __restrict__ src,
    const int* __restrict__ dst,
    const float* __restrict__ h2,
    float* __restrict__ out)
{
    const long long gid = (long long)blockIdx.x * blockDim.x + threadIdx.x;
    const int e = (int)(gid >> 4);
    const int c = (int)(gid & 15);
    if (e >= NE) return;

    const int s = __ldg(&src[e]);
    const int d = __ldg(&dst[e]);

    float4 v = ((const float4*)h2)[(size_t)s * 16 + c];
    float* p = out + (size_t)d * DIM + c * 4;
    asm volatile("red.global.add.v4.f32 [%0], {%1, %2, %3, %4};"
                 :: "l"(p), "f"(v.x), "f"(v.y), "f"(v.z), "f"(v.w)
                 : "memory");
}

// ---------------------------------------------------------------------------
// Kernel 3: in-place ReLU, vectorized.
// ---------------------------------------------------------------------------
__global__ __launch_bounds__(256) void relu_inplace(float4* __restrict__ out, int n4)
{
    int i = blockIdx.x * blockDim.x + threadIdx.x;
    if (i >= n4) return;
    float4 v = out[i];
    v.x = fmaxf(v.x, 0.f);
    v.y = fmaxf(v.y, 0.f);
    v.z = fmaxf(v.z, 0.f);
    v.w = fmaxf(v.w, 0.f);
    out[i] = v;
}

// ---------------------------------------------------------------------------
// Inputs (metadata order): x [N,64] f32, edge_index [2,E] i32, W1 [64,64] f32,
// W2 [64,64] f32. Output: [N,64] f32.
// ---------------------------------------------------------------------------
extern "C" void kernel_launch(void* const* d_in, const int* in_sizes, int n_in,
                              void* d_out, int out_size)
{
    const float* x   = (const float*)d_in[0];
    const int*   ei  = (const int*)d_in[1];
    const float* W1  = (const float*)d_in[2];
    const float* W2  = (const float*)d_in[3];
    float*       out = (float*)d_out;

    const int* src = ei;        // edge_index[0]
    const int* dst = ei + NE;   // edge_index[1]

    float* h2;
    cudaGetSymbolAddress((void**)&h2, g_h2);

    // 1) out = x@W1 (fully overwrites out), g_h2 = x@W2
    gemm_dual<<<NN / 32, 256>>>(x, W1, W2, out, h2);

    // 2) out[dst] += h2[src]  (16 threads per edge)
    const long long total = (long long)NE * 16;
    const int blocks = (int)((total + 255) / 256);
    scatter_edges<<<blocks, 256>>>(src, dst, h2, out);

    // 3) relu in place
    const int n4 = NN * DIM / 4;
    relu_inplace<<<(n4 + 255) / 256, 256>>>((float4*)out, n4);
}

// round 4
// speedup vs baseline: 2.7187x; 2.7187x over previous
#include <cuda_runtime.h>

#define NN 100000
#define DIM 64
#define NE 1250000

// scratch for h2 = x @ W2 (25.6 MB) — static device global, no allocation
__device__ float g_h2[NN * DIM];

// ---------------------------------------------------------------------------
// Kernel 1: dual GEMM, broadcast-weight formulation.
// Block: 256 threads = 8 warps, covers 64 rows.
//   warp w: mat = w>>2 (0: W1 -> h1, 1: W2 -> h2)
//           rowg = (w>>1)&1 (rows 32*rowg..+31), colg = w&1 (cols 32*colg..+31)
// Each lane owns one row, 32 output columns (16 f32x2 accumulators).
// Per k: 8x LDS.128 weight broadcast (warp-uniform address, conflict-free)
//        + 1 scalar x read (stride-65 rows -> banks (row+k)%32, conflict-free)
//        + 16 packed fma.rn.f32x2.
// Dynamic smem: sx[64][65] + sW1[4096] + sW2[4096] = 49408 B.
// ---------------------------------------------------------------------------
#define SX_STRIDE 65
#define SMEM_BYTES ((64 * SX_STRIDE + 4096 + 4096) * 4)

__global__ __launch_bounds__(256) void gemm_dual(
    const float* __restrict__ x,
    const float* __restrict__ W1,
    const float* __restrict__ W2,
    float* __restrict__ h1,
    float* __restrict__ h2)
{
    extern __shared__ float dsm[];
    float* sx  = dsm;                      // [64][65]
    float* sW1 = dsm + 64 * SX_STRIDE;     // [64][64] row-major (k, c)
    float* sW2 = sW1 + 4096;

    const int tid = threadIdx.x;

    // stage weights: 1024 float4 each
    const float4* w1v = (const float4*)W1;
    const float4* w2v = (const float4*)W2;
    #pragma unroll
    for (int i = tid; i < 1024; i += 256) {
        ((float4*)sW1)[i] = w1v[i];
        ((float4*)sW2)[i] = w2v[i];
    }

    // stage 64 rows of x (1024 float4), scalar STS into stride-65 rows
    const int rowBase = blockIdx.x * 64;
    const float4* x4 = (const float4*)(x + (size_t)rowBase * DIM);
    #pragma unroll
    for (int i = tid; i < 1024; i += 256) {
        const int r = i >> 4;
        const int c = (i & 15) * 4;
        float4 v = make_float4(0.f, 0.f, 0.f, 0.f);
        if (rowBase + r < NN) v = x4[i];
        float* p = sx + r * SX_STRIDE + c;
        p[0] = v.x; p[1] = v.y; p[2] = v.z; p[3] = v.w;
    }
    __syncthreads();

    const int lane = tid & 31;
    const int w    = tid >> 5;
    const int mat  = w >> 2;
    const int rowg = (w >> 1) & 1;
    const int colg = w & 1;

    const float* xrow  = sx + (rowg * 32 + lane) * SX_STRIDE;
    const float* wbase = (mat ? sW2 : sW1) + colg * 32;

    unsigned long long acc[16];
    #pragma unroll
    for (int i = 0; i < 16; i++) acc[i] = 0ULL;

    #pragma unroll 4
    for (int k = 0; k < 64; ++k) {
        const float xs = xrow[k];
        unsigned long long x2;
        asm("mov.b64 %0, {%1, %1};" : "=l"(x2) : "f"(xs));
        const ulonglong2* wr = (const ulonglong2*)(wbase + k * 64);
        #pragma unroll
        for (int i = 0; i < 8; ++i) {
            ulonglong2 wv = wr[i];   // 4 weight floats, 128-bit broadcast load
            asm("fma.rn.f32x2 %0, %1, %2, %0;" : "+l"(acc[2 * i])     : "l"(wv.x), "l"(x2));
            asm("fma.rn.f32x2 %0, %1, %2, %0;" : "+l"(acc[2 * i + 1]) : "l"(wv.y), "l"(x2));
        }
    }

    const int row = rowBase + rowg * 32 + lane;
    if (row < NN) {
        unsigned long long* o =
            (unsigned long long*)((mat ? h2 : h1) + (size_t)row * DIM + colg * 32);
        #pragma unroll
        for (int i = 0; i < 16; ++i) o[i] = acc[i];
    }
}

// ---------------------------------------------------------------------------
// Kernel 2: edge scatter. 16 threads per edge; each thread moves one float4
// via red.global.add.v4.f32 (single 128-bit L2 reduction).
// ---------------------------------------------------------------------------
__global__ __launch_bounds__(256) void scatter_edges(
    const int* __restrict__ src,
    const int* __restrict__ dst,
    const float* __restrict__ h2,
    float* __restrict__ out)
{
    const long long gid = (long long)blockIdx.x * blockDim.x + threadIdx.x;
    const int e = (int)(gid >> 4);
    const int c = (int)(gid & 15);
    if (e >= NE) return;

    const int s = __ldg(&src[e]);
    const int d = __ldg(&dst[e]);

    float4 v = ((const float4*)h2)[(size_t)s * 16 + c];
    float* p = out + (size_t)d * DIM + c * 4;
    asm volatile("red.global.add.v4.f32 [%0], {%1, %2, %3, %4};"
                 :: "l"(p), "f"(v.x), "f"(v.y), "f"(v.z), "f"(v.w)
                 : "memory");
}

// ---------------------------------------------------------------------------
// Kernel 3: in-place ReLU, vectorized.
// ---------------------------------------------------------------------------
__global__ __launch_bounds__(256) void relu_inplace(float4* __restrict__ out, int n4)
{
    int i = blockIdx.x * blockDim.x + threadIdx.x;
    if (i >= n4) return;
    float4 v = out[i];
    v.x = fmaxf(v.x, 0.f);
    v.y = fmaxf(v.y, 0.f);
    v.z = fmaxf(v.z, 0.f);
    v.w = fmaxf(v.w, 0.f);
    out[i] = v;
}

// ---------------------------------------------------------------------------
// Inputs (metadata order): x [N,64] f32, edge_index [2,E] i32, W1 [64,64] f32,
// W2 [64,64] f32. Output: [N,64] f32.
// ---------------------------------------------------------------------------
extern "C" void kernel_launch(void* const* d_in, const int* in_sizes, int n_in,
                              void* d_out, int out_size)
{
    const float* x   = (const float*)d_in[0];
    const int*   ei  = (const int*)d_in[1];
    const float* W1  = (const float*)d_in[2];
    const float* W2  = (const float*)d_in[3];
    float*       out = (float*)d_out;

    const int* src = ei;        // edge_index[0]
    const int* dst = ei + NE;   // edge_index[1]

    float* h2;
    cudaGetSymbolAddress((void**)&h2, g_h2);

    // dynamic smem > 48KB needs an explicit opt-in (host API, graph-safe)
    cudaFuncSetAttribute(gemm_dual, cudaFuncAttributeMaxDynamicSharedMemorySize,
                         SMEM_BYTES);

    // 1) out = x@W1 (fully overwrites out), g_h2 = x@W2
    gemm_dual<<<(NN + 63) / 64, 256, SMEM_BYTES>>>(x, W1, W2, out, h2);

    // 2) out[dst] += h2[src]  (16 threads per edge)
    const long long total = (long long)NE * 16;
    const int blocks = (int)((total + 255) / 256);
    scatter_edges<<<blocks, 256>>>(src, dst, h2, out);

    // 3) relu in place
    const int n4 = NN * DIM / 4;
    relu_inplace<<<(n4 + 255) / 256, 256>>>((float4*)out, n4);
}

// round 5
// speedup vs baseline: 3.0045x; 1.1051x over previous
#include <cuda_runtime.h>

#define NN 100000
#define DIM 64
#define NE 1250000

// scratch for h2 = x @ W2 (25.6 MB) — static device global, no allocation
__device__ float g_h2[NN * DIM];

// ---------------------------------------------------------------------------
// Kernel 1: dual GEMM, broadcast-weight + register row-blocking (R=2).
// Block: 256 threads = 8 warps, covers 128 rows, both matrices.
//   warp w: mat = w>>2 (0: W1 -> h1, 1: W2 -> h2)
//           rowg = (w>>1)&1 -> rows [rowg*64, rowg*64+64)
//           colg = w&1      -> cols [colg*32, colg*32+32)
// Each lane owns TWO rows (lane, lane+32 within its 64-row group) and 32
// output columns -> 2 x 16 f32x2 accumulators.
// Per k: 8x LDS.128 weight broadcast (warp-uniform, conflict-free) feeds
//        32 packed FFMA2; 2 scalar x reads (stride-65, conflict-free).
// Dynamic smem: sx[128][65] + sW1[4096] + sW2[4096] = 66048 B.
// ---------------------------------------------------------------------------
#define SX_STRIDE 65
#define SMEM_BYTES ((128 * SX_STRIDE + 4096 + 4096) * 4)

__global__ __launch_bounds__(256) void gemm_dual(
    const float* __restrict__ x,
    const float* __restrict__ W1,
    const float* __restrict__ W2,
    float* __restrict__ h1,
    float* __restrict__ h2)
{
    extern __shared__ float dsm[];
    float* sx  = dsm;                        // [128][65]
    float* sW1 = dsm + 128 * SX_STRIDE;      // [64][64] row-major (k, c)
    float* sW2 = sW1 + 4096;

    const int tid = threadIdx.x;

    // stage weights: 1024 float4 each
    const float4* w1v = (const float4*)W1;
    const float4* w2v = (const float4*)W2;
    #pragma unroll
    for (int i = tid; i < 1024; i += 256) {
        ((float4*)sW1)[i] = w1v[i];
        ((float4*)sW2)[i] = w2v[i];
    }

    // stage 128 rows of x (2048 float4), scalar STS into stride-65 rows
    const int rowBase = blockIdx.x * 128;
    const float4* x4 = (const float4*)(x + (size_t)rowBase * DIM);
    #pragma unroll
    for (int i = tid; i < 2048; i += 256) {
        const int r = i >> 4;
        const int c = (i & 15) * 4;
        float4 v = make_float4(0.f, 0.f, 0.f, 0.f);
        if (rowBase + r < NN) v = x4[i];
        float* p = sx + r * SX_STRIDE + c;
        p[0] = v.x; p[1] = v.y; p[2] = v.z; p[3] = v.w;
    }
    __syncthreads();

    const int lane = tid & 31;
    const int w    = tid >> 5;
    const int mat  = w >> 2;
    const int rowg = (w >> 1) & 1;
    const int colg = w & 1;

    const float* xr0  = sx + (rowg * 64 + lane) * SX_STRIDE;       // row A
    const float* xr1  = xr0 + 32 * SX_STRIDE;                      // row A+32
    const float* wbase = (mat ? sW2 : sW1) + colg * 32;

    unsigned long long acc0[16], acc1[16];
    #pragma unroll
    for (int i = 0; i < 16; i++) { acc0[i] = 0ULL; acc1[i] = 0ULL; }

    #pragma unroll 4
    for (int k = 0; k < 64; ++k) {
        const float xs0 = xr0[k];
        const float xs1 = xr1[k];
        unsigned long long xa, xb;
        asm("mov.b64 %0, {%1, %1};" : "=l"(xa) : "f"(xs0));
        asm("mov.b64 %0, {%1, %1};" : "=l"(xb) : "f"(xs1));
        const ulonglong2* wr = (const ulonglong2*)(wbase + k * 64);
        #pragma unroll
        for (int i = 0; i < 8; ++i) {
            ulonglong2 wv = wr[i];   // 4 weight floats, broadcast LDS.128
            asm("fma.rn.f32x2 %0, %1, %2, %0;" : "+l"(acc0[2 * i])     : "l"(wv.x), "l"(xa));
            asm("fma.rn.f32x2 %0, %1, %2, %0;" : "+l"(acc0[2 * i + 1]) : "l"(wv.y), "l"(xa));
            asm("fma.rn.f32x2 %0, %1, %2, %0;" : "+l"(acc1[2 * i])     : "l"(wv.x), "l"(xb));
            asm("fma.rn.f32x2 %0, %1, %2, %0;" : "+l"(acc1[2 * i + 1]) : "l"(wv.y), "l"(xb));
        }
    }

    float* hout = mat ? h2 : h1;
    const int r0 = rowBase + rowg * 64 + lane;
    const int r1 = r0 + 32;
    if (r0 < NN) {
        unsigned long long* o = (unsigned long long*)(hout + (size_t)r0 * DIM + colg * 32);
        #pragma unroll
        for (int i = 0; i < 16; ++i) o[i] = acc0[i];
    }
    if (r1 < NN) {
        unsigned long long* o = (unsigned long long*)(hout + (size_t)r1 * DIM + colg * 32);
        #pragma unroll
        for (int i = 0; i < 16; ++i) o[i] = acc1[i];
    }
}

// ---------------------------------------------------------------------------
// Kernel 2: edge scatter. 16 threads per edge; each thread moves one float4
// via red.global.add.v4.f32 (single 128-bit L2 reduction).
// ---------------------------------------------------------------------------
__global__ __launch_bounds__(256) void scatter_edges(
    const int* __restrict__ src,
    const int* __restrict__ dst,
    const float* __restrict__ h2,
    float* __restrict__ out)
{
    const long long gid = (long long)blockIdx.x * blockDim.x + threadIdx.x;
    const int e = (int)(gid >> 4);
    const int c = (int)(gid & 15);
    if (e >= NE) return;

    const int s = __ldg(&src[e]);
    const int d = __ldg(&dst[e]);

    float4 v = ((const float4*)h2)[(size_t)s * 16 + c];
    float* p = out + (size_t)d * DIM + c * 4;
    asm volatile("red.global.add.v4.f32 [%0], {%1, %2, %3, %4};"
                 :: "l"(p), "f"(v.x), "f"(v.y), "f"(v.z), "f"(v.w)
                 : "memory");
}

// ---------------------------------------------------------------------------
// Kernel 3: in-place ReLU, vectorized.
// ---------------------------------------------------------------------------
__global__ __launch_bounds__(256) void relu_inplace(float4* __restrict__ out, int n4)
{
    int i = blockIdx.x * blockDim.x + threadIdx.x;
    if (i >= n4) return;
    float4 v = out[i];
    v.x = fmaxf(v.x, 0.f);
    v.y = fmaxf(v.y, 0.f);
    v.z = fmaxf(v.z, 0.f);
    v.w = fmaxf(v.w, 0.f);
    out[i] = v;
}

// ---------------------------------------------------------------------------
// Inputs (metadata order): x [N,64] f32, edge_index [2,E] i32, W1 [64,64] f32,
// W2 [64,64] f32. Output: [N,64] f32.
// ---------------------------------------------------------------------------
extern "C" void kernel_launch(void* const* d_in, const int* in_sizes, int n_in,
                              void* d_out, int out_size)
{
    const float* x   = (const float*)d_in[0];
    const int*   ei  = (const int*)d_in[1];
    const float* W1  = (const float*)d_in[2];
    const float* W2  = (const float*)d_in[3];
    float*       out = (float*)d_out;

    const int* src = ei;        // edge_index[0]
    const int* dst = ei + NE;   // edge_index[1]

    float* h2;
    cudaGetSymbolAddress((void**)&h2, g_h2);

    // dynamic smem > 48KB needs an explicit opt-in (host API, graph-safe)
    cudaFuncSetAttribute(gemm_dual, cudaFuncAttributeMaxDynamicSharedMemorySize,
                         SMEM_BYTES);

    // 1) out = x@W1 (fully overwrites out), g_h2 = x@W2
    gemm_dual<<<(NN + 127) / 128, 256, SMEM_BYTES>>>(x, W1, W2, out, h2);

    // 2) out[dst] += h2[src]  (16 threads per edge)
    const long long total = (long long)NE * 16;
    const int blocks = (int)((total + 255) / 256);
    scatter_edges<<<blocks, 256>>>(src, dst, h2, out);

    // 3) relu in place
    const int n4 = NN * DIM / 4;
    relu_inplace<<<(n4 + 255) / 256, 256>>>((float4*)out, n4);
}